// round 1
// baseline (speedup 1.0000x reference)
#include <cuda_runtime.h>

// SSIM loss, fused single-pass per image band.
// pred/target: [32,1,512,512] f32. WIN=11, VALID -> 502x502 per image.
// out[0] = 1 - mean(S).

#define BATCH   32
#define HH      512
#define WW      512
#define WIN     11
#define OHH     502
#define OWW     502
#define NBANDS  16
#define RPB     32      // output rows per band (16*32 >= 502)

__device__ float g_partial[BATCH * NBANDS];

__global__ __launch_bounds__(128) void ssim_main(const float* __restrict__ pred,
                                                 const float* __restrict__ targ)
{
    const int band = blockIdx.x;
    const int img  = blockIdx.y;
    const int r0   = band * RPB;
    int rend = r0 + RPB - 1;
    if (rend > OHH - 1) rend = OHH - 1;

    const int t = threadIdx.x;
    const int c = t << 2;           // 4 output/input cols per thread, c in [0,508]

    // 5 vertical-sum rows staged per output row. Pad to 528 so horizontal
    // window reads up to col c+15 (<=523) stay in-bounds (garbage is masked).
    __shared__ __align__(16) float sv[5][528];
    __shared__ float wsum[4];

    const float* pb = pred + img * (HH * WW);
    const float* qb = targ + img * (HH * WW);

    float sx[4], sy[4], sxx[4], syy[4], sxy[4];
#pragma unroll
    for (int j = 0; j < 4; ++j) { sx[j]=0.f; sy[j]=0.f; sxx[j]=0.f; syy[j]=0.f; sxy[j]=0.f; }

    // Warm-up: vertical sums over rows r0 .. r0+9 (10 rows).
    for (int rr = r0; rr < r0 + WIN - 1; ++rr) {
        const float4 p4 = *(const float4*)(pb + rr * WW + c);
        const float4 q4 = *(const float4*)(qb + rr * WW + c);
        const float pj[4] = {p4.x, p4.y, p4.z, p4.w};
        const float qj[4] = {q4.x, q4.y, q4.z, q4.w};
#pragma unroll
        for (int j = 0; j < 4; ++j) {
            sx[j] += pj[j];
            sy[j] += qj[j];
            sxx[j] = fmaf(pj[j], pj[j], sxx[j]);
            syy[j] = fmaf(qj[j], qj[j], syy[j]);
            sxy[j] = fmaf(pj[j], qj[j], sxy[j]);
        }
    }

    const float inv_np = 1.0f / 121.0f;
    const float k120   = 1.0f / 120.0f;       // cov_norm / NP
    const float cn     = 121.0f / 120.0f;     // cov_norm
    const float C1     = 1.0e-4f;
    const float C2     = 9.0e-4f;

    float acc = 0.0f;

    for (int orow = r0; orow <= rend; ++orow) {
        // Load new bottom row (orow+10) and old top row (orow, L1-resident).
        const float4 pn4 = *(const float4*)(pb + (orow + WIN - 1) * WW + c);
        const float4 qn4 = *(const float4*)(qb + (orow + WIN - 1) * WW + c);
        const float4 po4 = *(const float4*)(pb + orow * WW + c);
        const float4 qo4 = *(const float4*)(qb + orow * WW + c);

        {   // add new row -> sums now cover rows orow..orow+10
            const float pj[4] = {pn4.x, pn4.y, pn4.z, pn4.w};
            const float qj[4] = {qn4.x, qn4.y, qn4.z, qn4.w};
#pragma unroll
            for (int j = 0; j < 4; ++j) {
                sx[j] += pj[j];
                sy[j] += qj[j];
                sxx[j] = fmaf(pj[j], pj[j], sxx[j]);
                syy[j] = fmaf(qj[j], qj[j], syy[j]);
                sxy[j] = fmaf(pj[j], qj[j], sxy[j]);
            }
        }

        // Stage vertical sums for this output row.
        *(float4*)&sv[0][c] = make_float4(sx[0],  sx[1],  sx[2],  sx[3]);
        *(float4*)&sv[1][c] = make_float4(sy[0],  sy[1],  sy[2],  sy[3]);
        *(float4*)&sv[2][c] = make_float4(sxx[0], sxx[1], sxx[2], sxx[3]);
        *(float4*)&sv[3][c] = make_float4(syy[0], syy[1], syy[2], syy[3]);
        *(float4*)&sv[4][c] = make_float4(sxy[0], sxy[1], sxy[2], sxy[3]);
        __syncthreads();

        // Horizontal 11-window sums for 4 outputs per quantity (sliding).
        float w[5][4];
#pragma unroll
        for (int q = 0; q < 5; ++q) {
            const float4 a0 = *(const float4*)&sv[q][c];
            const float4 a1 = *(const float4*)&sv[q][c + 4];
            const float4 a2 = *(const float4*)&sv[q][c + 8];
            const float4 a3 = *(const float4*)&sv[q][c + 12];
            float w0 = a0.x + a0.y + a0.z + a0.w
                     + a1.x + a1.y + a1.z + a1.w
                     + a2.x + a2.y + a2.z;                 // cols c..c+10
            float w1 = w0 - a0.x + a2.w;                    // c+1..c+11
            float w2 = w1 - a0.y + a3.x;                    // c+2..c+12
            float w3 = w2 - a0.z + a3.y;                    // c+3..c+13
            w[q][0] = w0; w[q][1] = w1; w[q][2] = w2; w[q][3] = w3;
        }
        __syncthreads();   // protect sv against next iteration's stores

        // SSIM per output pixel.
#pragma unroll
        for (int j = 0; j < 4; ++j) {
            const float ux  = w[0][j] * inv_np;
            const float uy  = w[1][j] * inv_np;
            const float ux2 = ux * ux;
            const float uy2 = uy * uy;
            const float uxy = ux * uy;
            const float vx  = fmaf(w[2][j], k120, -cn * ux2);
            const float vy  = fmaf(w[3][j], k120, -cn * uy2);
            const float vxy = fmaf(w[4][j], k120, -cn * uxy);
            const float A1  = fmaf(2.0f, uxy, C1);
            const float A2  = fmaf(2.0f, vxy, C2);
            const float B1  = ux2 + uy2 + C1;
            const float B2  = vx + vy + C2;
            const float S   = __fdividef(A1 * A2, B1 * B2);
            if (c + j < OWW) acc += S;
        }

        {   // subtract old top row -> sums cover orow+1..orow+10 for next iter
            const float pj[4] = {po4.x, po4.y, po4.z, po4.w};
            const float qj[4] = {qo4.x, qo4.y, qo4.z, qo4.w};
#pragma unroll
            for (int j = 0; j < 4; ++j) {
                sx[j] -= pj[j];
                sy[j] -= qj[j];
                sxx[j] = fmaf(-pj[j], pj[j], sxx[j]);
                syy[j] = fmaf(-qj[j], qj[j], syy[j]);
                sxy[j] = fmaf(-pj[j], qj[j], sxy[j]);
            }
        }
    }

    // Block reduction -> deterministic per-block slot.
    float v = acc;
#pragma unroll
    for (int off = 16; off; off >>= 1)
        v += __shfl_xor_sync(0xffffffffu, v, off);
    const int lane = t & 31, wid = t >> 5;
    if (lane == 0) wsum[wid] = v;
    __syncthreads();
    if (t == 0)
        g_partial[img * NBANDS + band] = wsum[0] + wsum[1] + wsum[2] + wsum[3];
}

__global__ void ssim_final(float* __restrict__ out)
{
    __shared__ double red[BATCH * NBANDS];
    const int t = threadIdx.x;
    red[t] = (double)g_partial[t];
    __syncthreads();
#pragma unroll
    for (int s = (BATCH * NBANDS) / 2; s > 0; s >>= 1) {
        if (t < s) red[t] += red[t + s];
        __syncthreads();
    }
    if (t == 0)
        out[0] = (float)(1.0 - red[0] / ((double)BATCH * OHH * OWW));
}

extern "C" void kernel_launch(void* const* d_in, const int* in_sizes, int n_in,
                              void* d_out, int out_size)
{
    const float* pred = (const float*)d_in[0];
    const float* targ = (const float*)d_in[1];
    float* out = (float*)d_out;

    ssim_main<<<dim3(NBANDS, BATCH), 128>>>(pred, targ);
    ssim_final<<<1, BATCH * NBANDS>>>(out);
}

// round 3
// speedup vs baseline: 1.0117x; 1.0117x over previous
#include <cuda_runtime.h>

// Fused SSIM loss. pred/target: [32,1,512,512] f32, WIN=11 VALID -> 502x502.
// out[0] = 1 - mean(S).
//
// One kernel: per-band fused box filters (vertical sliding register sums,
// horizontal via swizzled smem with 8 cols/thread), SSIM, block partials,
// and a deterministic last-block final reduction (atomic ticket).

#define BATCH   32
#define HH      512
#define WW      512
#define WIN     11
#define OHH     502
#define OWW     502
#define NBANDS  32
#define RPB     16
#define TPB     64
#define NBLK    (BATCH * NBANDS)   // 1024

__device__ float        g_partial[NBLK];
__device__ unsigned int g_count = 0;

// XOR swizzle on float4 index: makes stride-2 idx4 accesses conflict-free.
__device__ __forceinline__ int swz(int i4) { return i4 ^ ((i4 >> 3) & 7); }

__global__ __launch_bounds__(TPB) void ssim_main(const float* __restrict__ pred,
                                                 const float* __restrict__ targ,
                                                 float* __restrict__ out)
{
    const int band = blockIdx.x;
    const int img  = blockIdx.y;
    const int r0   = band * RPB;
    int rend = r0 + RPB - 1;
    if (rend > OHH - 1) rend = OHH - 1;

    const int t = threadIdx.x;          // 0..63
    const int c = t << 3;               // 8 cols per thread, c in [0,504]

    // Double-buffered staging of the 5 vertical sums, swizzled float4 layout.
    __shared__ float4 sv[2][5][136];
    __shared__ float  wsum[2];
    __shared__ int    is_last;
    __shared__ double dred[TPB];

    // Zero the pad region (phys float4 idx 128..135) of every q/buffer so
    // out-of-range halo reads are benign (never NaN).
    {
        const float4 z4 = make_float4(0.f, 0.f, 0.f, 0.f);
        for (int i = t; i < 80; i += TPB) {
            int b = i / 40, rem = i % 40;
            sv[b][rem / 8][128 + (rem & 7)] = z4;
        }
    }

    // Loop-invariant swizzled smem indices.
    const int i_s0 = swz(2 * t);
    const int i_s1 = swz(2 * t + 1);
    const int i_l0 = swz(2 * t + 2);
    const int i_l1 = swz(2 * t + 3);
    const int i_l2 = swz(2 * t + 4);

    const float* pb = pred + img * (HH * WW);
    const float* qb = targ + img * (HH * WW);

    float s[5][8];   // vertical sliding sums: x, y, xx, yy, xy
#pragma unroll
    for (int q = 0; q < 5; ++q)
#pragma unroll
        for (int j = 0; j < 8; ++j) s[q][j] = 0.f;

    // Warm-up: rows r0 .. r0+9.
    for (int rr = r0; rr < r0 + WIN - 1; ++rr) {
        const float4 p0 = *(const float4*)(pb + rr * WW + c);
        const float4 p1 = *(const float4*)(pb + rr * WW + c + 4);
        const float4 q0 = *(const float4*)(qb + rr * WW + c);
        const float4 q1 = *(const float4*)(qb + rr * WW + c + 4);
        const float pj[8] = {p0.x,p0.y,p0.z,p0.w,p1.x,p1.y,p1.z,p1.w};
        const float qj[8] = {q0.x,q0.y,q0.z,q0.w,q1.x,q1.y,q1.z,q1.w};
#pragma unroll
        for (int j = 0; j < 8; ++j) {
            s[0][j] += pj[j];
            s[1][j] += qj[j];
            s[2][j] = fmaf(pj[j], pj[j], s[2][j]);
            s[3][j] = fmaf(qj[j], qj[j], s[3][j]);
            s[4][j] = fmaf(pj[j], qj[j], s[4][j]);
        }
    }

    const float inv_np = 1.0f / 121.0f;
    const float k120   = 1.0f / 120.0f;     // cov_norm / NP
    const float cn     = 121.0f / 120.0f;   // cov_norm
    const float C1     = 1.0e-4f;
    const float C2     = 9.0e-4f;

    float acc = 0.0f;

    for (int orow = r0; orow <= rend; ++orow) {
        const int par = orow & 1;

        // New bottom row (orow+10) and old top row (orow).
        const float4 pn0 = *(const float4*)(pb + (orow + WIN - 1) * WW + c);
        const float4 pn1 = *(const float4*)(pb + (orow + WIN - 1) * WW + c + 4);
        const float4 qn0 = *(const float4*)(qb + (orow + WIN - 1) * WW + c);
        const float4 qn1 = *(const float4*)(qb + (orow + WIN - 1) * WW + c + 4);
        const float4 po0 = *(const float4*)(pb + orow * WW + c);
        const float4 po1 = *(const float4*)(pb + orow * WW + c + 4);
        const float4 qo0 = *(const float4*)(qb + orow * WW + c);
        const float4 qo1 = *(const float4*)(qb + orow * WW + c + 4);

        {   // add new row -> sums cover rows orow..orow+10
            const float pj[8] = {pn0.x,pn0.y,pn0.z,pn0.w,pn1.x,pn1.y,pn1.z,pn1.w};
            const float qj[8] = {qn0.x,qn0.y,qn0.z,qn0.w,qn1.x,qn1.y,qn1.z,qn1.w};
#pragma unroll
            for (int j = 0; j < 8; ++j) {
                s[0][j] += pj[j];
                s[1][j] += qj[j];
                s[2][j] = fmaf(pj[j], pj[j], s[2][j]);
                s[3][j] = fmaf(qj[j], qj[j], s[3][j]);
                s[4][j] = fmaf(pj[j], qj[j], s[4][j]);
            }
        }

        // Stage vertical sums (swizzled).
#pragma unroll
        for (int q = 0; q < 5; ++q) {
            sv[par][q][i_s0] = make_float4(s[q][0], s[q][1], s[q][2], s[q][3]);
            sv[par][q][i_s1] = make_float4(s[q][4], s[q][5], s[q][6], s[q][7]);
        }
        __syncthreads();

        // Horizontal 11-window sliding sums; own 8 values come from registers,
        // halo (cols c+8..c+19) from smem.
        float w[5][8];
#pragma unroll
        for (int q = 0; q < 5; ++q) {
            const float4 n0 = sv[par][q][i_l0];
            const float4 n1 = sv[par][q][i_l1];
            const float4 n2 = sv[par][q][i_l2];
            const float nb[10] = {n0.x,n0.y,n0.z,n0.w,n1.x,n1.y,n1.z,n1.w,n2.x,n2.y};
            float w0 = s[q][0] + s[q][1] + s[q][2] + s[q][3]
                     + s[q][4] + s[q][5] + s[q][6] + s[q][7]
                     + nb[0] + nb[1] + nb[2];              // cols c..c+10
            w[q][0] = w0;
#pragma unroll
            for (int j = 1; j < 8; ++j) {
                w0 = w0 - s[q][j - 1] + nb[j + 2];          // cols c+j..c+j+10
                w[q][j] = w0;
            }
        }

        // SSIM per output pixel.
#pragma unroll
        for (int j = 0; j < 8; ++j) {
            const float ux  = w[0][j] * inv_np;
            const float uy  = w[1][j] * inv_np;
            const float ux2 = ux * ux;
            const float uy2 = uy * uy;
            const float uxy = ux * uy;
            const float vx  = fmaf(w[2][j], k120, -cn * ux2);
            const float vy  = fmaf(w[3][j], k120, -cn * uy2);
            const float vxy = fmaf(w[4][j], k120, -cn * uxy);
            const float A1  = fmaf(2.0f, uxy, C1);
            const float A2  = fmaf(2.0f, vxy, C2);
            const float B1  = ux2 + uy2 + C1;
            const float B2  = vx + vy + C2;
            const float S   = __fdividef(A1 * A2, B1 * B2);
            if (c + j < OWW) acc += S;
        }

        {   // subtract old top row -> sums cover orow+1..orow+10
            const float pj[8] = {po0.x,po0.y,po0.z,po0.w,po1.x,po1.y,po1.z,po1.w};
            const float qj[8] = {qo0.x,qo0.y,qo0.z,qo0.w,qo1.x,qo1.y,qo1.z,qo1.w};
#pragma unroll
            for (int j = 0; j < 8; ++j) {
                s[0][j] -= pj[j];
                s[1][j] -= qj[j];
                s[2][j] = fmaf(-pj[j], pj[j], s[2][j]);
                s[3][j] = fmaf(-qj[j], qj[j], s[3][j]);
                s[4][j] = fmaf(-pj[j], qj[j], s[4][j]);
            }
        }
    }

    // Block reduction (2 warps).
    float v = acc;
#pragma unroll
    for (int off = 16; off; off >>= 1)
        v += __shfl_xor_sync(0xffffffffu, v, off);
    const int lane = t & 31, wid = t >> 5;
    if (lane == 0) wsum[wid] = v;
    __syncthreads();

    if (t == 0) {
        g_partial[img * NBANDS + band] = wsum[0] + wsum[1];
        __threadfence();
        const unsigned int tick = atomicAdd(&g_count, 1u);
        is_last = (tick == NBLK - 1);
    }
    __syncthreads();

    // Last block performs the deterministic final reduction.
    if (is_last) {
        __threadfence();
        double sd = 0.0;
        for (int i = t; i < NBLK; i += TPB)   // fixed slots, fixed order
            sd += (double)g_partial[i];
        dred[t] = sd;
        __syncthreads();
#pragma unroll
        for (int st = TPB / 2; st > 0; st >>= 1) {
            if (t < st) dred[t] += dred[t + st];
            __syncthreads();
        }
        if (t == 0) {
            out[0] = (float)(1.0 - dred[0] / ((double)BATCH * OHH * OWW));
            g_count = 0;   // reset for next graph replay
        }
    }
}

extern "C" void kernel_launch(void* const* d_in, const int* in_sizes, int n_in,
                              void* d_out, int out_size)
{
    const float* pred = (const float*)d_in[0];
    const float* targ = (const float*)d_in[1];
    float* out = (float*)d_out;

    ssim_main<<<dim3(NBANDS, BATCH), TPB>>>(pred, targ, out);
}